// round 8
// baseline (speedup 1.0000x reference)
#include <cuda_runtime.h>
#include <cuda_fp16.h>
#include <math.h>
#include <limits.h>
#include <stdint.h>

// Problem constants
#define CIN   256
#define COUT  64
#define KINST 1024
#define HW    80000   // 200*400
#define SIMT  0.9f

// ---------------- scratch (device globals; no allocation allowed) ----------
__device__ float g_mw[KINST * COUT];
__device__ float g_a[KINST * COUT];
__device__ unsigned char g_label[KINST * KINST];
__device__ unsigned char g_labelT[KINST * KINST];
__device__ int   g_pos2[KINST];
__device__ unsigned char g_keep[KINST];
__device__ __half g_merged_h[KINST * COUT];      // fp16 merged (GEMM A)
__device__ __half g_xh[(size_t)COUT * HW];       // fp16 x (GEMM B), 10.24 MB

// ---------------- PTX helpers ----------------------------------------------
__device__ __forceinline__ uint32_t smem_u32(const void* p) {
    uint32_t a;
    asm("{ .reg .u64 t; cvta.to.shared.u64 t, %1; cvt.u32.u64 %0, t; }" : "=r"(a) : "l"(p));
    return a;
}
__device__ __forceinline__ void cp_async16(uint32_t dst, const void* src) {
    asm volatile("cp.async.cg.shared.global [%0], [%1], 16;" :: "r"(dst), "l"(src));
}
__device__ __forceinline__ void cp_commit() {
    asm volatile("cp.async.commit_group;");
}
__device__ __forceinline__ void cp_wait0() {
    asm volatile("cp.async.wait_group 0;");
}
__device__ __forceinline__ void ldsm_x4(uint32_t r[4], uint32_t addr) {
    asm volatile("ldmatrix.sync.aligned.m8n8.x4.shared.b16 {%0,%1,%2,%3}, [%4];"
                 : "=r"(r[0]), "=r"(r[1]), "=r"(r[2]), "=r"(r[3]) : "r"(addr));
}
__device__ __forceinline__ void ldsm_x2t(uint32_t r[2], uint32_t addr) {
    asm volatile("ldmatrix.sync.aligned.m8n8.x2.trans.shared.b16 {%0,%1}, [%2];"
                 : "=r"(r[0]), "=r"(r[1]) : "r"(addr));
}
__device__ __forceinline__ void mma_f16(float c[4], const uint32_t a[4], const uint32_t b[2]) {
    asm volatile(
        "mma.sync.aligned.m16n8k16.row.col.f32.f16.f16.f32 "
        "{%0,%1,%2,%3}, {%4,%5,%6,%7}, {%8,%9}, {%0,%1,%2,%3};"
        : "+f"(c[0]), "+f"(c[1]), "+f"(c[2]), "+f"(c[3])
        : "r"(a[0]), "r"(a[1]), "r"(a[2]), "r"(a[3]), "r"(b[0]), "r"(b[1]));
}
__device__ __forceinline__ void stcs2(float* p, float2 v) {
    asm volatile("st.global.cs.v2.f32 [%0], {%1, %2};" :: "l"(p), "f"(v.x), "f"(v.y) : "memory");
}

// x -> fp16 conversion worker (chunk = 1024 elems)
__device__ __forceinline__ void xh_chunk(const float* __restrict__ x, int chunk)
{
    size_t i = ((size_t)chunk * 256 + threadIdx.x) * 4;
    float4 v = *(const float4*)&x[i];
    *(__half2*)&g_xh[i]     = __floats2half2_rn(v.x, v.y);
    *(__half2*)&g_xh[i + 2] = __floats2half2_rn(v.z, v.w);
}
#define XH_CHUNKS 5000      // 5000 * 1024 = COUT*HW
#define CONV_MW   1700
#define CONV_LB   1700
#define CONV_P2   1600

// ---------------- kernel A: mw = feat^T @ W^T + b ; a = normalize ----------
#define MWI 16
#define MW_BLK (KINST / MWI)    // 64
#define WSTR 65
#define FSTR 17
__global__ void k_mw(const float* __restrict__ feat,   // (CIN, KINST)
                     const float* __restrict__ W,      // (COUT, CIN)
                     const float* __restrict__ b,
                     const float* __restrict__ x)
{
    if (blockIdx.x >= MW_BLK) { xh_chunk(x, blockIdx.x - MW_BLK); return; }

    extern __shared__ float sm[];
    float* Wsm = sm;                     // [CIN][WSTR]
    float* ft  = sm + CIN * WSTR;        // [CIN][FSTR]
    float* red = ft + CIN * FSTR;        // [8 warps][4]

    int tid = threadIdx.x;
    int k0 = blockIdx.x * MWI;

    for (int idx = tid; idx < COUT * (CIN / 4); idx += 256) {
        int c = idx >> 6;
        int ci4 = (idx & 63) * 4;
        float4 v = *(const float4*)&W[c * CIN + ci4];
        Wsm[(ci4 + 0) * WSTR + c] = v.x;
        Wsm[(ci4 + 1) * WSTR + c] = v.y;
        Wsm[(ci4 + 2) * WSTR + c] = v.z;
        Wsm[(ci4 + 3) * WSTR + c] = v.w;
    }
    for (int idx = tid; idx < CIN * (MWI / 4); idx += 256) {
        int ci = idx >> 2;
        int kk4 = (idx & 3) * 4;
        float4 v = *(const float4*)&feat[ci * KINST + k0 + kk4];
        ft[ci * FSTR + kk4 + 0] = v.x;
        ft[ci * FSTR + kk4 + 1] = v.y;
        ft[ci * FSTR + kk4 + 2] = v.z;
        ft[ci * FSTR + kk4 + 3] = v.w;
    }
    __syncthreads();

    int c = tid & 63, tg = tid >> 6;
    float s[4] = {0.f, 0.f, 0.f, 0.f};
    #pragma unroll 4
    for (int ci = 0; ci < CIN; ci++) {
        float w = Wsm[ci * WSTR + c];
        const float* fr = &ft[ci * FSTR + tg];
        s[0] += fr[0] * w;
        s[1] += fr[4] * w;
        s[2] += fr[8] * w;
        s[3] += fr[12] * w;
    }
    float bc = b[c];
    #pragma unroll
    for (int q = 0; q < 4; q++) s[q] += bc;

    int warp = tid >> 5;
    #pragma unroll
    for (int q = 0; q < 4; q++) {
        float v = s[q] * s[q];
        #pragma unroll
        for (int o = 16; o > 0; o >>= 1) v += __shfl_xor_sync(0xffffffffu, v, o);
        if ((tid & 31) == 0) red[warp * 4 + q] = v;
    }
    __syncthreads();
    #pragma unroll
    for (int q = 0; q < 4; q++) {
        float tot = red[(tg * 2) * 4 + q] + red[(tg * 2 + 1) * 4 + q];
        float inv = 1.0f / fmaxf(sqrtf(tot), 1e-8f);
        int k = k0 + tg + 4 * q;
        g_mw[k * COUT + c] = s[q];
        g_a [k * COUT + c] = s[q] * inv;
    }
}
#define MW_SMEM ((CIN * WSTR + CIN * FSTR + 32) * 4)

// ---------------- kernel B: label = triu(sim>=T) & class-match -------------
#define TI 8
#define LB_BLK (KINST / TI)     // 128
#define AJSTR 65
__global__ void k_label(const int* __restrict__ cate, const float* __restrict__ x)
{
    if (blockIdx.x >= LB_BLK) { xh_chunk(x, CONV_MW + blockIdx.x - LB_BLK); return; }

    extern __shared__ float sm[];
    float* as  = sm;                     // [TI][COUT]
    float* ajs = sm + TI * COUT;         // [256][AJSTR]
    __shared__ int cs[TI];

    int tid = threadIdx.x;
    int i0 = blockIdx.x * TI;

    for (int idx = tid; idx < TI * COUT; idx += 256)
        as[idx] = g_a[(i0 + (idx >> 6)) * COUT + (idx & 63)];
    if (tid < TI) cs[tid] = cate[i0 + tid];

    for (int chunk = 0; chunk < 4; chunk++) {
        int jb = chunk * 256;
        __syncthreads();
        for (int idx = tid; idx < 256 * 16; idx += 256) {
            int j = idx >> 4;
            int c4 = (idx & 15) * 4;
            float4 v = *(const float4*)&g_a[(jb + j) * COUT + c4];
            float* d = &ajs[j * AJSTR + c4];
            d[0] = v.x; d[1] = v.y; d[2] = v.z; d[3] = v.w;
        }
        __syncthreads();

        int j = jb + tid;
        int cj = cate[j];
        float sim[TI];
        #pragma unroll
        for (int r = 0; r < TI; r++) sim[r] = 0.f;
        const float* aj = &ajs[tid * AJSTR];
        #pragma unroll 4
        for (int c = 0; c < COUT; c++) {
            float av = aj[c];
            #pragma unroll
            for (int r = 0; r < TI; r++) sim[r] += as[r * COUT + c] * av;
        }
        #pragma unroll
        for (int r = 0; r < TI; r++) {
            int i = i0 + r;
            unsigned char L = (j >= i) && (sim[r] >= SIMT) && (cj == cs[r]);
            g_label [i * KINST + j] = L;
            g_labelT[j * KINST + i] = L;
        }
    }
}
#define LB_SMEM ((TI * COUT + 256 * AJSTR) * 4)

// ---------------- kernel C: pos2/keep (warp per column) + conv -------------
#define POS2_BLOCKS 128
__global__ void k_pos2(const float* __restrict__ x)
{
    if (blockIdx.x >= POS2_BLOCKS) {
        xh_chunk(x, CONV_MW + CONV_LB + blockIdx.x - POS2_BLOCKS);
        return;
    }
    int warp = threadIdx.x >> 5, lane = threadIdx.x & 31;
    int j = blockIdx.x * 8 + warp;
    const uint4* col = (const uint4*)(g_labelT + j * KINST) + lane * 2;
    uint4 v0 = col[0], v1 = col[1];
    #define B4(w) (((w) | ((w) >> 7) | ((w) >> 14) | ((w) >> 21)) & 0xFu)
    uint32_t m = B4(v0.x) | (B4(v0.y) << 4) | (B4(v0.z) << 8)  | (B4(v0.w) << 12)
               | (B4(v1.x) << 16) | (B4(v1.y) << 20) | (B4(v1.z) << 24) | (B4(v1.w) << 28);
    #undef B4
    int f1 = 1 << 30, f2 = 1 << 30;
    if (m) {
        f1 = lane * 32 + __ffs(m) - 1;
        uint32_t m2 = m & (m - 1);
        if (m2) f2 = lane * 32 + __ffs(m2) - 1;
    }
    #pragma unroll
    for (int o = 16; o > 0; o >>= 1) {
        int o1 = __shfl_xor_sync(0xffffffffu, f1, o);
        int o2 = __shfl_xor_sync(0xffffffffu, f2, o);
        int n1 = min(f1, o1);
        int n2 = min(max(f1, o1), min(f2, o2));
        f1 = n1; f2 = n2;
    }
    if (lane == 0) {
        g_pos2[j] = f2;                 // index of 2nd label in column j (sentinel if <2)
        g_keep[j] = (f2 > j) ? 1 : 0;
    }
}

// ---------------- kernel D: merged (warp per instance) + fused tail --------
#define MG_BLOCKS 128
__global__ void k_merged_tail(const int* __restrict__ cate,
                              const float* __restrict__ score,
                              float* __restrict__ out)
{
    if (blockIdx.x >= MG_BLOCKS) {
        int j = (blockIdx.x - MG_BLOCKS) * 256 + threadIdx.x;
        if (j < KINST) {
            out[(size_t)KINST * HW + j]             = g_keep[j] ? 1.0f : 0.0f;
            out[(size_t)KINST * HW + KINST + j]     = (float)cate[j];
            out[(size_t)KINST * HW + 2 * KINST + j] = score[j];
        }
        return;
    }
    int warp = threadIdx.x >> 5, lane = threadIdx.x & 31;
    int i = blockIdx.x * 8 + warp;

    uint32_t mk = 0;
    if (g_keep[i]) {
        const uint4* row = (const uint4*)(g_label + i * KINST) + lane * 2;
        uint4 v0 = row[0], v1 = row[1];
        #define B4(w) (((w) | ((w) >> 7) | ((w) >> 14) | ((w) >> 21)) & 0xFu)
        mk = B4(v0.x) | (B4(v0.y) << 4) | (B4(v0.z) << 8)  | (B4(v0.w) << 12)
           | (B4(v1.x) << 16) | (B4(v1.y) << 20) | (B4(v1.z) << 24) | (B4(v1.w) << 28);
        #undef B4
    }
    float a0 = 0.f, a1 = 0.f;
    int m = 0;
    while (true) {
        uint32_t active = __ballot_sync(0xffffffffu, mk != 0);
        if (!active) break;
        int src = __ffs(active) - 1;
        uint32_t ml = __shfl_sync(0xffffffffu, mk, src);
        int j = src * 32 + __ffs(ml) - 1;
        if (lane == src) mk &= mk - 1;
        if (i < g_pos2[j]) {
            a0 += g_mw[j * COUT + lane];
            a1 += g_mw[j * COUT + 32 + lane];
            m++;
        }
    }
    float d = (m > 0) ? (float)m : 1.0f;
    g_merged_h[i * COUT + lane]      = __float2half_rn(a0 / d);
    g_merged_h[i * COUT + 32 + lane] = __float2half_rn(a1 / d);
}

// ---------------- kernel F: inst = merged @ x, fp16 mma, pipelined ---------
// Grid (625, 4). Block: N-tile of 128 cols, loops 2 M-tiles of 128 rows.
#define BM 128
#define BN 128
#define MTILES 2
#define ASTRH 72
#define BSTRH 136

__global__ void __launch_bounds__(256, 2)
k_inst_mma(float* __restrict__ out)
{
    __shared__ __align__(16) __half bs_h[64 * BSTRH];        // 17 KB
    __shared__ __align__(16) __half as_h[2][BM * ASTRH];     // 2 x 18 KB

    int tid = threadIdx.x;
    int wid = tid >> 5, lid = tid & 31;
    int n0 = blockIdx.x * BN;
    int mbase = blockIdx.y * (MTILES * BM);

    uint32_t b_s  = smem_u32(bs_h);
    uint32_t a_s0 = smem_u32(as_h[0]);
    uint32_t a_s1 = smem_u32(as_h[1]);

    #pragma unroll
    for (int t = 0; t < 4; t++) {
        int idx = tid + t * 256;
        int k = idx >> 4, c16 = idx & 15;
        cp_async16(b_s + (k * BSTRH + c16 * 8) * 2,
                   &g_xh[(size_t)k * HW + n0 + c16 * 8]);
    }
    #pragma unroll
    for (int t = 0; t < 4; t++) {
        int idx = tid + t * 256;
        int m = idx >> 3, c16 = idx & 7;
        cp_async16(a_s0 + (m * ASTRH + c16 * 8) * 2,
                   &g_merged_h[(mbase + m) * COUT + c16 * 8]);
    }
    cp_commit();

    int wm = (wid >> 2) * 64;
    int wn = (wid & 3) * 32;
    int lrow = lid & 15, lhalf = lid >> 4;
    int g = lid >> 2, c4 = lid & 3;

    uint32_t b_base = b_s + (lrow * BSTRH + wn) * 2;

    for (int mt = 0; mt < MTILES; mt++) {
        cp_wait0();
        __syncthreads();

        if (mt + 1 < MTILES) {
            uint32_t a_nxt = (mt & 1) ? a_s0 : a_s1;
            int mb = mbase + (mt + 1) * BM;
            #pragma unroll
            for (int t = 0; t < 4; t++) {
                int idx = tid + t * 256;
                int m = idx >> 3, c16 = idx & 7;
                cp_async16(a_nxt + (m * ASTRH + c16 * 8) * 2,
                           &g_merged_h[(mb + m) * COUT + c16 * 8]);
            }
            cp_commit();
        }

        uint32_t a_cur = (mt & 1) ? a_s1 : a_s0;
        uint32_t a_base = a_cur + ((wm + lrow) * ASTRH + lhalf * 8) * 2;

        float acc[4][4][4];
        #pragma unroll
        for (int mf = 0; mf < 4; mf++)
            #pragma unroll
            for (int nf = 0; nf < 4; nf++)
                #pragma unroll
                for (int q = 0; q < 4; q++) acc[mf][nf][q] = 0.f;

        #pragma unroll
        for (int ks = 0; ks < 4; ks++) {
            uint32_t a[4][4], bfr[4][2];
            #pragma unroll
            for (int mf = 0; mf < 4; mf++)
                ldsm_x4(a[mf], a_base + mf * 16 * (ASTRH * 2) + ks * 32);
            #pragma unroll
            for (int nf = 0; nf < 4; nf++)
                ldsm_x2t(bfr[nf], b_base + ks * 16 * (BSTRH * 2) + nf * 16);
            #pragma unroll
            for (int nf = 0; nf < 4; nf++)
                #pragma unroll
                for (int mf = 0; mf < 4; mf++)
                    mma_f16(acc[mf][nf], a[mf], bfr[nf]);
        }

        int m0 = mbase + mt * BM;
        #pragma unroll
        for (int mf = 0; mf < 4; mf++) {
            size_t r0 = (size_t)(m0 + wm + mf * 16 + g) * HW + n0;
            #pragma unroll
            for (int nf = 0; nf < 4; nf++) {
                int col = wn + nf * 8 + 2 * c4;
                stcs2(&out[r0 + col],          make_float2(acc[mf][nf][0], acc[mf][nf][1]));
                stcs2(&out[r0 + 8 * HW + col], make_float2(acc[mf][nf][2], acc[mf][nf][3]));
            }
        }
    }
}

// ---------------------------------------------------------------------------
extern "C" void kernel_launch(void* const* d_in, const int* in_sizes, int n_in,
                              void* d_out, int out_size)
{
    const float* x        = (const float*)d_in[0];
    const float* idx_feat = (const float*)d_in[1];
    const int*   cate     = (const int*)  d_in[2];
    const float* score    = (const float*)d_in[3];
    const float* W        = (const float*)d_in[4];
    const float* b        = (const float*)d_in[5];
    float* out = (float*)d_out;

    static bool attr_set = false;
    if (!attr_set) {
        cudaFuncSetAttribute(k_mw,    cudaFuncAttributeMaxDynamicSharedMemorySize, MW_SMEM);
        cudaFuncSetAttribute(k_label, cudaFuncAttributeMaxDynamicSharedMemorySize, LB_SMEM);
        attr_set = true;
    }

    k_mw<<<MW_BLK + CONV_MW, 256, MW_SMEM>>>(idx_feat, W, b, x);
    k_label<<<LB_BLK + CONV_LB, 256, LB_SMEM>>>(cate, x);
    k_pos2<<<POS2_BLOCKS + CONV_P2, 256>>>(x);
    k_merged_tail<<<MG_BLOCKS + 4, 256>>>(cate, score, out);

    dim3 grid(HW / BN, KINST / (MTILES * BM));   // (625, 4)
    k_inst_mma<<<grid, 256>>>(out);
}